// round 3
// baseline (speedup 1.0000x reference)
#include <cuda_runtime.h>

typedef unsigned long long ull;

// ---- SoA weight planes: cos / sin / -sin ----
__device__ float g_w1c[16],   g_w1s[16],   g_w1n[16];    // [co*4 + i*2 + j]
__device__ float g_w2c[544],  g_w2s[544],  g_w2n[544];   // [co*68 + (c*16+i*4+j)] (pad 64->68)
__device__ float g_wfc[2880], g_wfs[2880], g_wfn[2880];  // [o*288 + f]

__global__ void prep_kernel(const float* __restrict__ w1,
                            const float* __restrict__ w2,
                            const float* __restrict__ wf) {
    int t = threadIdx.x;
    if (t < 16) {
        float s, c; __sincosf(w1[t], &s, &c);
        g_w1c[t] = c; g_w1s[t] = s; g_w1n[t] = -s;
    }
    for (int i = t; i < 512; i += blockDim.x) {
        int co = i >> 6, r = i & 63;
        float s, c; __sincosf(w2[i], &s, &c);
        int d = co * 68 + r;
        g_w2c[d] = c; g_w2s[d] = s; g_w2n[d] = -s;
    }
    for (int i = t; i < 2880; i += blockDim.x) {
        int f = i / 10, o = i % 10;
        float s, c; __sincosf(wf[i], &s, &c);
        int d = o * 288 + f;
        g_wfc[d] = c; g_wfs[d] = s; g_wfn[d] = -s;
    }
}

// packed dual-FMA: acc(lo,hi) += a(lo,hi) * b(lo,hi)
static __device__ __forceinline__ void ffma2(ull& acc, ull a, ull b) {
    asm("fma.rn.f32x2 %0, %1, %2, %0;" : "+l"(acc) : "l"(a), "l"(b));
}
static __device__ __forceinline__ float f2lo(ull v) { return __uint_as_float((unsigned)v); }
static __device__ __forceinline__ float f2hi(ull v) { return __uint_as_float((unsigned)(v >> 32)); }

__global__ __launch_bounds__(320, 3) void ring_kernel(const float* __restrict__ x,
                                                      float* __restrict__ out) {
    __shared__ __align__(16) float s_pxc[784], s_pxs[784];   // pixel (cos,sin), 28x28
    __shared__ __align__(16) float s_h1c[896], s_h1s[896];   // conv1 out [c*224 + y*16 + x]
    __shared__ __align__(16) float s_h2c[288], s_h2s[288];   // conv2 out [(ho*6+wo)*8 + co]
    __shared__ __align__(16) float s_w1c[16],  s_w1s[16],  s_w1n[16];
    __shared__ __align__(16) float s_w2c[544], s_w2s[544], s_w2n[544];

    const int tid = threadIdx.x;

    // ---- Stage 0: pixel trig (float4 loads) + weight staging ----
    const float4* xb4 = reinterpret_cast<const float4*>(x + blockIdx.x * 784);
    for (int i = tid; i < 196; i += 320) {
        float4 v = xb4[i];
        float s, c;
        __sincosf(v.x, &s, &c); s_pxc[4*i+0] = c; s_pxs[4*i+0] = s;
        __sincosf(v.y, &s, &c); s_pxc[4*i+1] = c; s_pxs[4*i+1] = s;
        __sincosf(v.z, &s, &c); s_pxc[4*i+2] = c; s_pxs[4*i+2] = s;
        __sincosf(v.w, &s, &c); s_pxc[4*i+3] = c; s_pxs[4*i+3] = s;
    }
    if (tid < 16) {
        s_w1c[tid] = g_w1c[tid]; s_w1s[tid] = g_w1s[tid]; s_w1n[tid] = g_w1n[tid];
    }
    for (int i = tid; i < 544; i += 320) {
        s_w2c[i] = g_w2c[i]; s_w2s[i] = g_w2s[i]; s_w2n[i] = g_w2n[i];
    }
    __syncthreads();

    // ---- Stage 1: conv1 2x2 s2 -> 14x14x4 ----
    for (int idx = tid; idx < 784; idx += 320) {
        int co = idx / 196, p = idx % 196;
        int py = p / 14, px = p % 14;
        int base = py * 56 + px * 2;
        ull vc0 = *(const ull*)&s_pxc[base];
        ull vs0 = *(const ull*)&s_pxs[base];
        ull vc1 = *(const ull*)&s_pxc[base + 28];
        ull vs1 = *(const ull*)&s_pxs[base + 28];
        ulonglong2 wc = *(const ulonglong2*)&s_w1c[co * 4];
        ulonglong2 ws = *(const ulonglong2*)&s_w1s[co * 4];
        ulonglong2 wn = *(const ulonglong2*)&s_w1n[co * 4];
        ull S = 0, T = 0;
        ffma2(S, vc0, wc.x); ffma2(S, vc1, wc.y);
        ffma2(S, vs0, ws.x); ffma2(S, vs1, ws.y);
        ffma2(T, vs0, wc.x); ffma2(T, vs1, wc.y);
        ffma2(T, vc0, wn.x); ffma2(T, vc1, wn.y);
        float Sx = f2lo(S) + f2hi(S);
        float Sy = f2lo(T) + f2hi(T);
        float r = rsqrtf(fmaxf(Sx * Sx + Sy * Sy, 1e-30f));
        int dst = co * 224 + py * 16 + px;
        s_h1c[dst] = Sx * r; s_h1s[dst] = Sy * r;
    }
    __syncthreads();

    // ---- Stage 2: conv2 4x4 s2, 4->8 ch -> 288 outputs; 4 outputs/thread ----
    // active window of 72 threads rotated per block for SMSP balance
    int st = tid - ((blockIdx.x & 3) << 5);
    if (st >= 0 && st < 72) {
        int co2 = st & 3, q = st >> 2;        // co in {co2, co2+4}
        int ho = q / 3, wp = q % 3;           // wo in {2wp, 2wp+1}
        const int vb0 = ho * 32 + wp * 4;
        const int wbA = co2 * 68, wbB = (co2 + 4) * 68;
        ull SA = 0, TA = 0, SB = 0, TB = 0, SC = 0, TC = 0, SD = 0, TD = 0;
#pragma unroll
        for (int c = 0; c < 4; c++) {
#pragma unroll
            for (int i = 0; i < 4; i++) {
                int vb = c * 224 + vb0 + i * 16;
                ull vc0 = *(const ull*)&s_h1c[vb];
                ull vc1 = *(const ull*)&s_h1c[vb + 2];
                ull vc2 = *(const ull*)&s_h1c[vb + 4];
                ull vs0 = *(const ull*)&s_h1s[vb];
                ull vs1 = *(const ull*)&s_h1s[vb + 2];
                ull vs2 = *(const ull*)&s_h1s[vb + 4];
                int wb = c * 16 + i * 4;
                {   // co = co2
                    ulonglong2 wc = *(const ulonglong2*)&s_w2c[wbA + wb];
                    ulonglong2 ws = *(const ulonglong2*)&s_w2s[wbA + wb];
                    ulonglong2 wn = *(const ulonglong2*)&s_w2n[wbA + wb];
                    ffma2(SA, vc0, wc.x); ffma2(SA, vc1, wc.y);
                    ffma2(SA, vs0, ws.x); ffma2(SA, vs1, ws.y);
                    ffma2(TA, vs0, wc.x); ffma2(TA, vs1, wc.y);
                    ffma2(TA, vc0, wn.x); ffma2(TA, vc1, wn.y);
                    ffma2(SB, vc1, wc.x); ffma2(SB, vc2, wc.y);
                    ffma2(SB, vs1, ws.x); ffma2(SB, vs2, ws.y);
                    ffma2(TB, vs1, wc.x); ffma2(TB, vs2, wc.y);
                    ffma2(TB, vc1, wn.x); ffma2(TB, vc2, wn.y);
                }
                {   // co = co2 + 4
                    ulonglong2 wc = *(const ulonglong2*)&s_w2c[wbB + wb];
                    ulonglong2 ws = *(const ulonglong2*)&s_w2s[wbB + wb];
                    ulonglong2 wn = *(const ulonglong2*)&s_w2n[wbB + wb];
                    ffma2(SC, vc0, wc.x); ffma2(SC, vc1, wc.y);
                    ffma2(SC, vs0, ws.x); ffma2(SC, vs1, ws.y);
                    ffma2(TC, vs0, wc.x); ffma2(TC, vs1, wc.y);
                    ffma2(TC, vc0, wn.x); ffma2(TC, vc1, wn.y);
                    ffma2(SD, vc1, wc.x); ffma2(SD, vc2, wc.y);
                    ffma2(SD, vs1, ws.x); ffma2(SD, vs2, ws.y);
                    ffma2(TD, vs1, wc.x); ffma2(TD, vs2, wc.y);
                    ffma2(TD, vc1, wn.x); ffma2(TD, vc2, wn.y);
                }
            }
        }
        int d0 = (ho * 6 + 2 * wp) * 8 + co2;
        {
            float Sx = f2lo(SA) + f2hi(SA), Sy = f2lo(TA) + f2hi(TA);
            float r = rsqrtf(fmaxf(Sx * Sx + Sy * Sy, 1e-30f));
            s_h2c[d0] = Sx * r; s_h2s[d0] = Sy * r;
        }
        {
            float Sx = f2lo(SB) + f2hi(SB), Sy = f2lo(TB) + f2hi(TB);
            float r = rsqrtf(fmaxf(Sx * Sx + Sy * Sy, 1e-30f));
            s_h2c[d0 + 8] = Sx * r; s_h2s[d0 + 8] = Sy * r;
        }
        {
            float Sx = f2lo(SC) + f2hi(SC), Sy = f2lo(TC) + f2hi(TC);
            float r = rsqrtf(fmaxf(Sx * Sx + Sy * Sy, 1e-30f));
            s_h2c[d0 + 4] = Sx * r; s_h2s[d0 + 4] = Sy * r;
        }
        {
            float Sx = f2lo(SD) + f2hi(SD), Sy = f2lo(TD) + f2hi(TD);
            float r = rsqrtf(fmaxf(Sx * Sx + Sy * Sy, 1e-30f));
            s_h2c[d0 + 12] = Sx * r; s_h2s[d0 + 12] = Sy * r;
        }
    }
    __syncthreads();

    // ---- Stage 3: FF ring layer, one warp per class ----
    int o = tid >> 5, lane = tid & 31;
    const ull* wfc = reinterpret_cast<const ull*>(g_wfc) + o * 144;
    const ull* wfs = reinterpret_cast<const ull*>(g_wfs) + o * 144;
    const ull* wfn = reinterpret_cast<const ull*>(g_wfn) + o * 144;
    ull S = 0, T = 0;
    for (int p = lane; p < 144; p += 32) {
        ull vc = *(const ull*)&s_h2c[2 * p];
        ull vs = *(const ull*)&s_h2s[2 * p];
        ull wc = __ldg(wfc + p);
        ull ws = __ldg(wfs + p);
        ull wn = __ldg(wfn + p);
        ffma2(S, vc, wc); ffma2(S, vs, ws);
        ffma2(T, vs, wc); ffma2(T, vc, wn);
    }
    float Sx = f2lo(S) + f2hi(S);
    float Sy = f2lo(T) + f2hi(T);
#pragma unroll
    for (int off = 16; off; off >>= 1) {
        Sx += __shfl_xor_sync(0xffffffff, Sx, off);
        Sy += __shfl_xor_sync(0xffffffff, Sy, off);
    }
    if (lane == 0)
        out[blockIdx.x * 10 + o] = Sy * rsqrtf(fmaxf(Sx * Sx + Sy * Sy, 1e-30f));
}

extern "C" void kernel_launch(void* const* d_in, const int* in_sizes, int n_in,
                              void* d_out, int out_size) {
    const float* x  = (const float*)d_in[0];
    const float* w1 = (const float*)d_in[1];
    const float* w2 = (const float*)d_in[2];
    const float* wf = (const float*)d_in[3];
    float* out = (float*)d_out;
    int B = in_sizes[0] / 784;
    prep_kernel<<<1, 512>>>(w1, w2, wf);
    ring_kernel<<<B, 320>>>(x, out);
}

// round 4
// speedup vs baseline: 1.2256x; 1.2256x over previous
#include <cuda_runtime.h>

typedef unsigned long long ull;

// ---- SoA weight planes (cos / sin) ----
__device__ __align__(16) float g_w1c[16],   g_w1s[16];     // [co*4 + i*2 + j]
__device__ __align__(16) float g_w2c[544],  g_w2s[544];    // [co*68 + (c*16+i*4+j)]
__device__ __align__(16) float g_wfc[2880], g_wfs[2880];   // [o*288 + f]

__global__ void prep_kernel(const float* __restrict__ w1,
                            const float* __restrict__ w2,
                            const float* __restrict__ wf) {
    int t = threadIdx.x;
    if (t < 16) {
        float s, c; sincosf(w1[t], &s, &c);
        g_w1c[t] = c; g_w1s[t] = s;
    }
    for (int i = t; i < 512; i += blockDim.x) {
        int co = i >> 6, r = i & 63;
        float s, c; sincosf(w2[i], &s, &c);
        g_w2c[co * 68 + r] = c; g_w2s[co * 68 + r] = s;
    }
    for (int i = t; i < 2880; i += blockDim.x) {
        int f = i / 10, o = i % 10;
        float s, c; sincosf(wf[i], &s, &c);
        g_wfc[o * 288 + f] = c; g_wfs[o * 288 + f] = s;
    }
}

// packed dual-FMA: acc(lo,hi) += a(lo,hi) * b(lo,hi)
static __device__ __forceinline__ void ffma2(ull& acc, ull a, ull b) {
    asm("fma.rn.f32x2 %0, %1, %2, %0;" : "+l"(acc) : "l"(a), "l"(b));
}
static __device__ __forceinline__ float f2lo(ull v) { return __uint_as_float((unsigned)v); }
static __device__ __forceinline__ float f2hi(ull v) { return __uint_as_float((unsigned)(v >> 32)); }

// MUFU-free sincos: quadrant reduction + minimax polys (FMA/ALU pipes only)
static __device__ __forceinline__ void fast_sincos(float x, float& s, float& c) {
    float t = fmaf(x, 0.63661977236758134f, 12582912.0f);   // round(x*2/pi) + 1.5*2^23
    unsigned q = __float_as_uint(t);                         // low 2 bits = k mod 4
    float kf = t - 12582912.0f;
    float r = fmaf(kf, -1.57079625129699707031f, x);
    r = fmaf(kf, -7.54978941586159e-08f, r);
    float y = r * r;
    // sin(r) = r + r*y*(S1 + y*(S2 + y*S3))
    float ps = fmaf(y, -1.95152959e-4f, 8.33216087e-3f);
    ps = fmaf(y, ps, -1.66666546e-1f);
    float s0 = fmaf(r * y, ps, r);
    // cos(r) = 1 + y*(C1 + y*(C2 + y*(C3 + y*C4)))
    float pc = fmaf(y, 2.44331571e-5f, -1.38873162e-3f);
    pc = fmaf(y, pc, 4.16666232e-2f);
    pc = fmaf(y, pc, -0.5f);
    float c0 = fmaf(y, pc, 1.0f);
    // quadrant rotation
    bool sw = q & 1u;
    float ss = sw ? c0 : s0;
    float cc = sw ? s0 : c0;
    unsigned sgs = (q & 2u) << 30;
    unsigned sgc = ((q + 1u) & 2u) << 30;
    s = __uint_as_float(__float_as_uint(ss) ^ sgs);
    c = __uint_as_float(__float_as_uint(cc) ^ sgc);
}

// MUFU-free rsqrt: bit trick + 2 Newton iterations (~5e-6 rel err)
static __device__ __forceinline__ float fast_rsqrt(float d) {
    float y = __uint_as_float(0x5F3759DFu - (__float_as_uint(d) >> 1));
    float h = 0.5f * d;
    y = y * fmaf(-(h * y), y, 1.5f);
    y = y * fmaf(-(h * y), y, 1.5f);
    return y;
}

__global__ __launch_bounds__(320, 4) void ring_kernel(const float* __restrict__ x,
                                                      float* __restrict__ out) {
    __shared__ __align__(16) float s_pxc[784], s_pxs[784];   // pixel (cos,sin), 28x28
    __shared__ __align__(16) float s_h1c[896], s_h1s[896];   // conv1 out [c*224 + y*16 + x]
    __shared__ __align__(16) float s_h2c[288], s_h2s[288];   // conv2 out [(ho*6+wo)*8 + co]
    __shared__ __align__(16) float s_w1c[16],  s_w1s[16];
    __shared__ __align__(16) float s_w2c[544], s_w2s[544];

    const int tid = threadIdx.x;

    // ---- Stage 0: pixel trig (float4 loads, poly sincos) + weight staging ----
    const float4* xb4 = reinterpret_cast<const float4*>(x + blockIdx.x * 784);
    for (int i = tid; i < 196; i += 320) {
        float4 v = xb4[i];
        float s, c;
        fast_sincos(v.x, s, c); s_pxc[4*i+0] = c; s_pxs[4*i+0] = s;
        fast_sincos(v.y, s, c); s_pxc[4*i+1] = c; s_pxs[4*i+1] = s;
        fast_sincos(v.z, s, c); s_pxc[4*i+2] = c; s_pxs[4*i+2] = s;
        fast_sincos(v.w, s, c); s_pxc[4*i+3] = c; s_pxs[4*i+3] = s;
    }
    if (tid < 16) { s_w1c[tid] = g_w1c[tid]; s_w1s[tid] = g_w1s[tid]; }
    for (int i = tid; i < 544; i += 320) { s_w2c[i] = g_w2c[i]; s_w2s[i] = g_w2s[i]; }
    __syncthreads();

    // ---- Stage 1: conv1 2x2 s2 -> 14x14x4; one spatial pos/thread, 4 co in regs ----
    if (tid < 196) {
        int py = tid / 14, px = tid % 14;
        int base = py * 56 + px * 2;
        ull vc0 = *(const ull*)&s_pxc[base];
        ull vs0 = *(const ull*)&s_pxs[base];
        ull vc1 = *(const ull*)&s_pxc[base + 28];
        ull vs1 = *(const ull*)&s_pxs[base + 28];
        int dst0 = py * 16 + px;
#pragma unroll
        for (int co = 0; co < 4; co++) {
            ulonglong2 wc = *(const ulonglong2*)&s_w1c[co * 4];
            ulonglong2 ws = *(const ulonglong2*)&s_w1s[co * 4];
            ull S = 0, T3 = 0, T4 = 0;
            ffma2(S,  vc0, wc.x); ffma2(S,  vc1, wc.y);
            ffma2(S,  vs0, ws.x); ffma2(S,  vs1, ws.y);
            ffma2(T3, vs0, wc.x); ffma2(T3, vs1, wc.y);
            ffma2(T4, vc0, ws.x); ffma2(T4, vc1, ws.y);
            float Sx = f2lo(S) + f2hi(S);
            float Sy = (f2lo(T3) + f2hi(T3)) - (f2lo(T4) + f2hi(T4));
            float r = fast_rsqrt(fmaxf(Sx * Sx + Sy * Sy, 1e-30f));
            s_h1c[co * 224 + dst0] = Sx * r;
            s_h1s[co * 224 + dst0] = Sy * r;
        }
    }
    __syncthreads();

    // ---- Stage 2: conv2 4x4 s2, 4->8 ch -> 288 outputs; 2 outputs/thread (wo pair) ----
    int st = tid - ((blockIdx.x & 3) << 5);   // rotate active window for SMSP balance
    if (st >= 0 && st < 144) {
        int co = st & 7, q = st >> 3;          // co fastest -> v broadcast in 8-lane groups
        int ho = q / 3, wp = q % 3;            // outputs wo = 2wp, 2wp+1
        const int vb0 = ho * 32 + wp * 4;
        const int wb0 = co * 68;
        ull SA = 0, TA3 = 0, TA4 = 0, SB = 0, TB3 = 0, TB4 = 0;
#pragma unroll
        for (int c = 0; c < 4; c++) {
#pragma unroll
            for (int i = 0; i < 4; i++) {
                int vb = c * 224 + vb0 + i * 16;
                ull vc0 = *(const ull*)&s_h1c[vb];
                ull vc1 = *(const ull*)&s_h1c[vb + 2];
                ull vc2 = *(const ull*)&s_h1c[vb + 4];
                ull vs0 = *(const ull*)&s_h1s[vb];
                ull vs1 = *(const ull*)&s_h1s[vb + 2];
                ull vs2 = *(const ull*)&s_h1s[vb + 4];
                int wb = wb0 + c * 16 + i * 4;
                ulonglong2 wc = *(const ulonglong2*)&s_w2c[wb];
                ulonglong2 ws = *(const ulonglong2*)&s_w2s[wb];
                // output A: px 0..3
                ffma2(SA,  vc0, wc.x); ffma2(SA,  vc1, wc.y);
                ffma2(SA,  vs0, ws.x); ffma2(SA,  vs1, ws.y);
                ffma2(TA3, vs0, wc.x); ffma2(TA3, vs1, wc.y);
                ffma2(TA4, vc0, ws.x); ffma2(TA4, vc1, ws.y);
                // output B: px 2..5
                ffma2(SB,  vc1, wc.x); ffma2(SB,  vc2, wc.y);
                ffma2(SB,  vs1, ws.x); ffma2(SB,  vs2, ws.y);
                ffma2(TB3, vs1, wc.x); ffma2(TB3, vs2, wc.y);
                ffma2(TB4, vc1, ws.x); ffma2(TB4, vc2, ws.y);
            }
        }
        int d0 = (ho * 6 + 2 * wp) * 8 + co;
        {
            float Sx = f2lo(SA) + f2hi(SA);
            float Sy = (f2lo(TA3) + f2hi(TA3)) - (f2lo(TA4) + f2hi(TA4));
            float r = fast_rsqrt(fmaxf(Sx * Sx + Sy * Sy, 1e-30f));
            s_h2c[d0] = Sx * r; s_h2s[d0] = Sy * r;
        }
        {
            float Sx = f2lo(SB) + f2hi(SB);
            float Sy = (f2lo(TB3) + f2hi(TB3)) - (f2lo(TB4) + f2hi(TB4));
            float r = fast_rsqrt(fmaxf(Sx * Sx + Sy * Sy, 1e-30f));
            s_h2c[d0 + 8] = Sx * r; s_h2s[d0 + 8] = Sy * r;
        }
    }
    __syncthreads();

    // ---- Stage 3: FF ring layer, one warp per class; wf straight from global ----
    int o = tid >> 5, lane = tid & 31;
    const ull* wfc = reinterpret_cast<const ull*>(g_wfc) + o * 144;
    const ull* wfs = reinterpret_cast<const ull*>(g_wfs) + o * 144;
    ull S = 0, T3 = 0, T4 = 0;
    for (int p = lane; p < 144; p += 32) {
        ull vc = *(const ull*)&s_h2c[2 * p];
        ull vs = *(const ull*)&s_h2s[2 * p];
        ull wc = __ldg(wfc + p);
        ull ws = __ldg(wfs + p);
        ffma2(S,  vc, wc); ffma2(S,  vs, ws);
        ffma2(T3, vs, wc); ffma2(T4, vc, ws);
    }
    float Sx = f2lo(S) + f2hi(S);
    float Sy = (f2lo(T3) + f2hi(T3)) - (f2lo(T4) + f2hi(T4));
#pragma unroll
    for (int off = 16; off; off >>= 1) {
        Sx += __shfl_xor_sync(0xffffffff, Sx, off);
        Sy += __shfl_xor_sync(0xffffffff, Sy, off);
    }
    if (lane == 0)
        out[blockIdx.x * 10 + o] = Sy * fast_rsqrt(fmaxf(Sx * Sx + Sy * Sy, 1e-30f));
}

extern "C" void kernel_launch(void* const* d_in, const int* in_sizes, int n_in,
                              void* d_out, int out_size) {
    const float* x  = (const float*)d_in[0];
    const float* w1 = (const float*)d_in[1];
    const float* w2 = (const float*)d_in[2];
    const float* wf = (const float*)d_in[3];
    float* out = (float*)d_out;
    int B = in_sizes[0] / 784;
    prep_kernel<<<1, 512>>>(w1, w2, wf);
    ring_kernel<<<B, 320>>>(x, out);
}